// round 5
// baseline (speedup 1.0000x reference)
#include <cuda_runtime.h>
#include <cstdint>

// Problem constants
#define SDIM   64
#define CIN    16
#define COUTC  16
#define BATCH  4

// Tiling: each block computes 8 couts (half), full x row, TY y-rows, one z.
#define TY         4
#define TXT        8
#define XPT        8
#define NTHREADS 128
#define COUT_BLK   8          // couts per block
#define CPT        2          // couts per thread (one FFMA2 pair)

// Windowed input tile: 8 windows of 10 floats per row (conflict-free LDS.64)
#define WIN_W      10
#define NWIN       8
#define IN_ROW     (NWIN * WIN_W)     // 80
#define IN_H       (TY + 2)           // 6
#define IN_D       3
#define TILE_ELEMS (IN_D * IN_H * IN_ROW)   // 1440
#define SLOTS_PER_THREAD ((TILE_ELEMS + NTHREADS - 1) / NTHREADS)  // 12

// Shared weights for this block's 8 couts: [(cin*3+kd)*3+kh][kw*8 + cout_local]
#define W_ROW   (3 * COUT_BLK)              // 24
#define W_ELEMS (CIN * 9 * W_ROW)           // 3456 floats = 13.8KB

#define PACKF2(d, lo, hi) \
    asm("mov.b64 %0, {%1, %2};" : "=l"(d) : "f"(lo), "f"(hi))
#define FMAF2(d, a, b, c) \
    asm("fma.rn.f32x2 %0, %1, %2, %3;" : "=l"(d) : "l"(a), "l"(b), "l"(c))
#define UNPACKF2(lo, hi, s) \
    asm("mov.b64 {%0, %1}, %2;" : "=f"(lo), "=f"(hi) : "l"(s))

__device__ __forceinline__ uint32_t smem_u32(const void* p) {
    return (uint32_t)__cvta_generic_to_shared(p);
}

__global__ void __launch_bounds__(NTHREADS, 7)
conv3d_kernel(const float* __restrict__ X,
              const float* __restrict__ Wg,
              const float* __restrict__ Bias,
              float* __restrict__ Out)
{
    __shared__ __align__(16) float s_w[W_ELEMS];
    __shared__ float s_bias[COUT_BLK];
    __shared__ __align__(16) float s_in[2][TILE_ELEMS];

    const int tid = threadIdx.x;
    const int tx  = tid & (TXT - 1);
    const int ty  = (tid >> 3) & (TY - 1);
    const int cg  = tid >> 5;               // cout pair index 0..3

    const int z   = blockIdx.x;
    const int y0  = blockIdx.y * TY;
    const int ch  = blockIdx.z & 1;         // cout half
    const int b   = blockIdx.z >> 1;        // batch
    const int c00 = ch * COUT_BLK;          // first global cout of this block

    // ---- Weights for this block's 8 couts: load + transpose into shared ----
    for (int g = tid; g < COUT_BLK * CIN * 27; g += NTHREADS) {
        int cl   = g / (CIN * 27);          // local cout 0..7
        int rem  = g % (CIN * 27);
        int cin  = rem / 27;
        int k    = rem % 27;
        int kdh  = k / 3;
        int kw   = k % 3;
        s_w[(cin * 9 + kdh) * W_ROW + kw * COUT_BLK + cl] =
            Wg[((size_t)(c00 + cl) * CIN + cin) * 27 + k];
    }
    if (tid < COUT_BLK) s_bias[tid] = Bias[c00 + tid];

    // ---- Precompute tile-slot source offsets (cin-invariant) ----
    int soff[SLOTS_PER_THREAD];
#pragma unroll
    for (int k = 0; k < SLOTS_PER_THREAD; ++k) {
        int s = tid + k * NTHREADS;
        int off = -1;
        if (s < TILE_ELEMS) {
            int r  = s / IN_ROW;
            int p  = s % IN_ROW;
            int w  = p / WIN_W;
            int o  = p % WIN_W;
            int gx = 8 * w + o - 1;
            int gz = z  + r / IN_H - 1;
            int gy = y0 + r % IN_H - 1;
            if ((unsigned)gz < SDIM && (unsigned)gy < SDIM && (unsigned)gx < SDIM)
                off = (gz * SDIM + gy) * SDIM + gx;
            else {
                s_in[0][s] = 0.0f;
                s_in[1][s] = 0.0f;
            }
        }
        soff[k] = off;
    }
    __syncthreads();   // zeros + weights visible before compute / overwrite

    const float* Xb = X + (size_t)b * CIN * (SDIM * SDIM * SDIM);

    // ---- Prologue: async-load tile for cin=0 into buffer 0 ----
    {
#pragma unroll
        for (int k = 0; k < SLOTS_PER_THREAD; ++k) {
            if (soff[k] >= 0) {
                uint32_t dst = smem_u32(&s_in[0][tid + k * NTHREADS]);
                asm volatile("cp.async.ca.shared.global [%0], [%1], 4;"
                             :: "r"(dst), "l"(Xb + soff[k]));
            }
        }
        asm volatile("cp.async.commit_group;");
    }

    // One cout-pair x 8 x positions
    unsigned long long accd[XPT];
#pragma unroll
    for (int j = 0; j < XPT; ++j) accd[j] = 0ull;

#pragma unroll 1
    for (int cin = 0; cin < CIN; ++cin) {
        asm volatile("cp.async.wait_group 0;");
        __syncthreads();

        if (cin + 1 < CIN) {
            const float* Xc = Xb + (size_t)(cin + 1) * (SDIM * SDIM * SDIM);
            float* buf = s_in[(cin + 1) & 1];
#pragma unroll
            for (int k = 0; k < SLOTS_PER_THREAD; ++k) {
                if (soff[k] >= 0) {
                    uint32_t dst = smem_u32(&buf[tid + k * NTHREADS]);
                    asm volatile("cp.async.ca.shared.global [%0], [%1], 4;"
                                 :: "r"(dst), "l"(Xc + soff[k]));
                }
            }
            asm volatile("cp.async.commit_group;");
        }

        // ---- Compute: conflict-free window loads + FFMA2 on one cout pair ----
        const float* cur = s_in[cin & 1];
        const float* wci = s_w + cin * 9 * W_ROW + cg * CPT;
#pragma unroll
        for (int kd = 0; kd < 3; ++kd) {
#pragma unroll
            for (int kh = 0; kh < 3; ++kh) {
                const float* rowp = cur + (kd * IN_H + ty + kh) * IN_ROW + tx * WIN_W;
                const float2* r2 = reinterpret_cast<const float2*>(rowp);
                unsigned long long dup[WIN_W];
#pragma unroll
                for (int i = 0; i < 5; ++i) {
                    float2 p = r2[i];
                    PACKF2(dup[2 * i],     p.x, p.x);
                    PACKF2(dup[2 * i + 1], p.y, p.y);
                }

                const float* wp = wci + (kd * 3 + kh) * W_ROW;
                unsigned long long wA[3];
#pragma unroll
                for (int kw = 0; kw < 3; ++kw)
                    wA[kw] = *reinterpret_cast<const unsigned long long*>(wp + kw * COUT_BLK);

#pragma unroll
                for (int kw = 0; kw < 3; ++kw)
#pragma unroll
                    for (int j = 0; j < XPT; ++j)
                        FMAF2(accd[j], dup[j + kw], wA[kw], accd[j]);
            }
        }
    }

    // ---- Epilogue: unpack, bias, vectorized stores ----
    const int x0 = tx * XPT;
    const int y  = y0 + ty;
    {
        float o0[XPT], o1[XPT];
#pragma unroll
        for (int j = 0; j < XPT; ++j) UNPACKF2(o0[j], o1[j], accd[j]);

        const int c0 = c00 + cg * CPT;      // global cout of pair
        const float b0 = s_bias[cg * CPT];
        const float b1 = s_bias[cg * CPT + 1];

        float* op0 = Out + ((((size_t)b * COUTC + c0)     * SDIM + z) * SDIM + y) * SDIM + x0;
        float* op1 = Out + ((((size_t)b * COUTC + c0 + 1) * SDIM + z) * SDIM + y) * SDIM + x0;

        reinterpret_cast<float4*>(op0)[0] = make_float4(o0[0] + b0, o0[1] + b0, o0[2] + b0, o0[3] + b0);
        reinterpret_cast<float4*>(op0)[1] = make_float4(o0[4] + b0, o0[5] + b0, o0[6] + b0, o0[7] + b0);
        reinterpret_cast<float4*>(op1)[0] = make_float4(o1[0] + b1, o1[1] + b1, o1[2] + b1, o1[3] + b1);
        reinterpret_cast<float4*>(op1)[1] = make_float4(o1[4] + b1, o1[5] + b1, o1[6] + b1, o1[7] + b1);
    }
}

extern "C" void kernel_launch(void* const* d_in, const int* in_sizes, int n_in,
                              void* d_out, int out_size)
{
    const float* x    = (const float*)d_in[0];
    const float* w    = (const float*)d_in[1];
    const float* bias = (const float*)d_in[2];
    float* out        = (float*)d_out;

    dim3 grid(SDIM, SDIM / TY, BATCH * 2);   // (z, y-tiles, batch*cout-halves)
    conv3d_kernel<<<grid, NTHREADS>>>(x, w, bias, out);
}

// round 6
// speedup vs baseline: 1.0011x; 1.0011x over previous
#include <cuda_runtime.h>
#include <cstdint>

// Problem constants
#define SDIM   64
#define CIN    16
#define COUTC  16
#define BATCH  4

// Tiling: each block computes 8 couts (half), full x row, TY y-rows, one z.
#define TY         4
#define TXT        8
#define XPT        8
#define NTHREADS 128
#define COUT_BLK   8          // couts per block
#define CPT        2          // couts per thread (one FFMA2 pair)

// Windowed input tile: 8 windows of 10 floats per row (conflict-free LDS.64)
#define WIN_W      10
#define NWIN       8
#define IN_ROW     (NWIN * WIN_W)     // 80
#define IN_H       (TY + 2)           // 6
#define IN_D       3
#define TILE_ELEMS (IN_D * IN_H * IN_ROW)   // 1440
#define SLOTS_PER_THREAD ((TILE_ELEMS + NTHREADS - 1) / NTHREADS)  // 12

// Shared weights for this block's 8 couts: [(cin*3+kd)*3+kh][kw*8 + cout_local]
#define W_ROW   (3 * COUT_BLK)              // 24
#define W_ELEMS (CIN * 9 * W_ROW)           // 3456 floats = 13.8KB

#define PACKF2(d, lo, hi) \
    asm("mov.b64 %0, {%1, %2};" : "=l"(d) : "f"(lo), "f"(hi))
#define FMAF2(d, a, b, c) \
    asm("fma.rn.f32x2 %0, %1, %2, %3;" : "=l"(d) : "l"(a), "l"(b), "l"(c))
#define UNPACKF2(lo, hi, s) \
    asm("mov.b64 {%0, %1}, %2;" : "=f"(lo), "=f"(hi) : "l"(s))

__device__ __forceinline__ uint32_t smem_u32(const void* p) {
    return (uint32_t)__cvta_generic_to_shared(p);
}

__global__ void __launch_bounds__(NTHREADS, 7)
conv3d_kernel(const float* __restrict__ X,
              const float* __restrict__ Wg,
              const float* __restrict__ Bias,
              float* __restrict__ Out)
{
    __shared__ __align__(16) float s_w[W_ELEMS];
    __shared__ float s_bias[COUT_BLK];
    __shared__ __align__(16) float s_in[2][TILE_ELEMS];

    const int tid = threadIdx.x;
    const int tx  = tid & (TXT - 1);
    const int ty  = (tid >> 3) & (TY - 1);
    const int cg  = tid >> 5;               // cout pair index 0..3

    const int z   = blockIdx.x;
    const int y0  = blockIdx.y * TY;
    const int ch  = blockIdx.z & 1;         // cout half
    const int b   = blockIdx.z >> 1;        // batch
    const int c00 = ch * COUT_BLK;          // first global cout of this block

    // ---- Weights for this block's 8 couts: load + transpose into shared ----
    for (int g = tid; g < COUT_BLK * CIN * 27; g += NTHREADS) {
        int cl   = g / (CIN * 27);          // local cout 0..7
        int rem  = g % (CIN * 27);
        int cin  = rem / 27;
        int k    = rem % 27;
        int kdh  = k / 3;
        int kw   = k % 3;
        s_w[(cin * 9 + kdh) * W_ROW + kw * COUT_BLK + cl] =
            Wg[((size_t)(c00 + cl) * CIN + cin) * 27 + k];
    }
    if (tid < COUT_BLK) s_bias[tid] = Bias[c00 + tid];

    // ---- Precompute tile-slot source offsets (cin-invariant) ----
    int soff[SLOTS_PER_THREAD];
#pragma unroll
    for (int k = 0; k < SLOTS_PER_THREAD; ++k) {
        int s = tid + k * NTHREADS;
        int off = -1;
        if (s < TILE_ELEMS) {
            int r  = s / IN_ROW;
            int p  = s % IN_ROW;
            int w  = p / WIN_W;
            int o  = p % WIN_W;
            int gx = 8 * w + o - 1;
            int gz = z  + r / IN_H - 1;
            int gy = y0 + r % IN_H - 1;
            if ((unsigned)gz < SDIM && (unsigned)gy < SDIM && (unsigned)gx < SDIM)
                off = (gz * SDIM + gy) * SDIM + gx;
            else {
                s_in[0][s] = 0.0f;
                s_in[1][s] = 0.0f;
            }
        }
        soff[k] = off;
    }
    __syncthreads();   // zeros + weights visible before compute / overwrite

    const float* Xb = X + (size_t)b * CIN * (SDIM * SDIM * SDIM);

    // ---- Prologue: async-load tile for cin=0 into buffer 0 ----
    {
#pragma unroll
        for (int k = 0; k < SLOTS_PER_THREAD; ++k) {
            if (soff[k] >= 0) {
                uint32_t dst = smem_u32(&s_in[0][tid + k * NTHREADS]);
                asm volatile("cp.async.ca.shared.global [%0], [%1], 4;"
                             :: "r"(dst), "l"(Xb + soff[k]));
            }
        }
        asm volatile("cp.async.commit_group;");
    }

    // One cout-pair x 8 x positions
    unsigned long long accd[XPT];
#pragma unroll
    for (int j = 0; j < XPT; ++j) accd[j] = 0ull;

#pragma unroll 1
    for (int cin = 0; cin < CIN; ++cin) {
        asm volatile("cp.async.wait_group 0;");
        __syncthreads();

        if (cin + 1 < CIN) {
            const float* Xc = Xb + (size_t)(cin + 1) * (SDIM * SDIM * SDIM);
            float* buf = s_in[(cin + 1) & 1];
#pragma unroll
            for (int k = 0; k < SLOTS_PER_THREAD; ++k) {
                if (soff[k] >= 0) {
                    uint32_t dst = smem_u32(&buf[tid + k * NTHREADS]);
                    asm volatile("cp.async.ca.shared.global [%0], [%1], 4;"
                                 :: "r"(dst), "l"(Xc + soff[k]));
                }
            }
            asm volatile("cp.async.commit_group;");
        }

        // ---- Compute: conflict-free window loads + FFMA2 on one cout pair ----
        const float* cur = s_in[cin & 1];
        const float* wci = s_w + cin * 9 * W_ROW + cg * CPT;
#pragma unroll
        for (int kd = 0; kd < 3; ++kd) {
#pragma unroll
            for (int kh = 0; kh < 3; ++kh) {
                const float* rowp = cur + (kd * IN_H + ty + kh) * IN_ROW + tx * WIN_W;
                const float2* r2 = reinterpret_cast<const float2*>(rowp);
                unsigned long long dup[WIN_W];
#pragma unroll
                for (int i = 0; i < 5; ++i) {
                    float2 p = r2[i];
                    PACKF2(dup[2 * i],     p.x, p.x);
                    PACKF2(dup[2 * i + 1], p.y, p.y);
                }

                const float* wp = wci + (kd * 3 + kh) * W_ROW;
                unsigned long long wA[3];
#pragma unroll
                for (int kw = 0; kw < 3; ++kw)
                    wA[kw] = *reinterpret_cast<const unsigned long long*>(wp + kw * COUT_BLK);

#pragma unroll
                for (int kw = 0; kw < 3; ++kw)
#pragma unroll
                    for (int j = 0; j < XPT; ++j)
                        FMAF2(accd[j], dup[j + kw], wA[kw], accd[j]);
            }
        }
    }

    // ---- Epilogue: unpack, bias, vectorized stores ----
    const int x0 = tx * XPT;
    const int y  = y0 + ty;
    {
        float o0[XPT], o1[XPT];
#pragma unroll
        for (int j = 0; j < XPT; ++j) UNPACKF2(o0[j], o1[j], accd[j]);

        const int c0 = c00 + cg * CPT;      // global cout of pair
        const float b0 = s_bias[cg * CPT];
        const float b1 = s_bias[cg * CPT + 1];

        float* op0 = Out + ((((size_t)b * COUTC + c0)     * SDIM + z) * SDIM + y) * SDIM + x0;
        float* op1 = Out + ((((size_t)b * COUTC + c0 + 1) * SDIM + z) * SDIM + y) * SDIM + x0;

        reinterpret_cast<float4*>(op0)[0] = make_float4(o0[0] + b0, o0[1] + b0, o0[2] + b0, o0[3] + b0);
        reinterpret_cast<float4*>(op0)[1] = make_float4(o0[4] + b0, o0[5] + b0, o0[6] + b0, o0[7] + b0);
        reinterpret_cast<float4*>(op1)[0] = make_float4(o1[0] + b1, o1[1] + b1, o1[2] + b1, o1[3] + b1);
        reinterpret_cast<float4*>(op1)[1] = make_float4(o1[4] + b1, o1[5] + b1, o1[6] + b1, o1[7] + b1);
    }
}

extern "C" void kernel_launch(void* const* d_in, const int* in_sizes, int n_in,
                              void* d_out, int out_size)
{
    const float* x    = (const float*)d_in[0];
    const float* w    = (const float*)d_in[1];
    const float* bias = (const float*)d_in[2];
    float* out        = (float*)d_out;

    dim3 grid(SDIM, SDIM / TY, BATCH * 2);   // (z, y-tiles, batch*cout-halves)
    conv3d_kernel<<<grid, NTHREADS>>>(x, w, bias, out);
}

// round 7
// speedup vs baseline: 1.1599x; 1.1586x over previous
#include <cuda_runtime.h>
#include <cstdint>

// Problem constants
#define SDIM   64
#define CIN    16
#define COUTC  16
#define BATCH  4

// Tiling (R4 shape: 16 couts per block, 4 per thread)
#define TY         4
#define TXT        8
#define XPT        8
#define CPT        4
#define NTHREADS 128

// Windowed input tile: 8 windows of 10 floats per row (conflict-free LDS.64)
#define WIN_W      10
#define NWIN       8
#define IN_ROW     (NWIN * WIN_W)     // 80
#define IN_H       (TY + 2)           // 6
#define IN_D       3
#define TILE_ELEMS (IN_D * IN_H * IN_ROW)   // 1440
#define IN_SLOTS   ((TILE_ELEMS + NTHREADS - 1) / NTHREADS)  // 12

// Per-cin weight slice, transposed: [kd*3+kh][kw*16 + cout] = 9*48 = 432 floats
#define W_SLICE   432
#define W_SLOTS   ((W_SLICE + NTHREADS - 1) / NTHREADS)      // 4

#define PACKF2(d, lo, hi) \
    asm("mov.b64 %0, {%1, %2};" : "=l"(d) : "f"(lo), "f"(hi))
#define FMAF2(d, a, b, c) \
    asm("fma.rn.f32x2 %0, %1, %2, %3;" : "=l"(d) : "l"(a), "l"(b), "l"(c))
#define UNPACKF2(lo, hi, s) \
    asm("mov.b64 {%0, %1}, %2;" : "=f"(lo), "=f"(hi) : "l"(s))

__device__ __forceinline__ uint32_t smem_u32(const void* p) {
    return (uint32_t)__cvta_generic_to_shared(p);
}

__global__ void __launch_bounds__(NTHREADS, 6)
conv3d_kernel(const float* __restrict__ X,
              const float* __restrict__ Wg,
              const float* __restrict__ Bias,
              float* __restrict__ Out)
{
    __shared__ __align__(16) float s_in[2][TILE_ELEMS];      // 11.5 KB
    __shared__ __align__(16) float s_wbuf[2][W_SLICE];       // 3.5 KB
    __shared__ int   s_soff[IN_SLOTS * NTHREADS];            // 6 KB
    __shared__ float s_bias[COUTC];

    const int tid = threadIdx.x;
    const int tx  = tid & (TXT - 1);
    const int ty  = (tid >> 3) & (TY - 1);
    const int cg  = tid >> 5;

    const int z  = blockIdx.x;
    const int y0 = blockIdx.y * TY;
    const int b  = blockIdx.z;

    // ---- Precompute input tile-slot source offsets -> shared (cin-invariant) ----
    for (int k = 0; k < IN_SLOTS; ++k) {
        int s = tid + k * NTHREADS;
        int off = -1;
        if (s < TILE_ELEMS) {
            int r  = s / IN_ROW;
            int p  = s % IN_ROW;
            int w  = p / WIN_W;
            int o  = p % WIN_W;
            int gx = 8 * w + o - 1;
            int gz = z  + r / IN_H - 1;
            int gy = y0 + r % IN_H - 1;
            if ((unsigned)gz < SDIM && (unsigned)gy < SDIM && (unsigned)gx < SDIM)
                off = (gz * SDIM + gy) * SDIM + gx;
            else {
                s_in[0][s] = 0.0f;    // zero halo once in both buffers
                s_in[1][s] = 0.0f;
            }
        }
        s_soff[k * NTHREADS + tid] = off;
    }

    // ---- Precompute weight-slice slot mappings (cin-invariant, kept in regs) ----
    // slice element g: cout = g/27, k = g%27 ; src off (per cin base) = cout*432 + k
    // dst = (k/3)*48 + (k%3)*16 + cout
    int wsoff[W_SLOTS], wdoff[W_SLOTS];
#pragma unroll
    for (int j = 0; j < W_SLOTS; ++j) {
        int g = tid + j * NTHREADS;
        if (g < W_SLICE) {
            int cout = g / 27;
            int k    = g % 27;
            wsoff[j] = cout * (CIN * 27) + k;
            wdoff[j] = (k / 3) * 48 + (k % 3) * 16 + cout;
        } else {
            wsoff[j] = -1;
            wdoff[j] = 0;
        }
    }
    if (tid < COUTC) s_bias[tid] = Bias[tid];
    __syncthreads();   // halo zeros + s_soff visible

    const float* Xb = X + (size_t)b * CIN * (SDIM * SDIM * SDIM);

    // ---- Prologue: async-load input tile + weight slice for cin=0 ----
    {
#pragma unroll
        for (int k = 0; k < IN_SLOTS; ++k) {
            int off = s_soff[k * NTHREADS + tid];
            if (off >= 0) {
                uint32_t dst = smem_u32(&s_in[0][tid + k * NTHREADS]);
                asm volatile("cp.async.ca.shared.global [%0], [%1], 4;"
                             :: "r"(dst), "l"(Xb + off));
            }
        }
        const float* Wc = Wg;   // cin = 0
#pragma unroll
        for (int j = 0; j < W_SLOTS; ++j) {
            if (wsoff[j] >= 0) {
                uint32_t dst = smem_u32(&s_wbuf[0][wdoff[j]]);
                asm volatile("cp.async.ca.shared.global [%0], [%1], 4;"
                             :: "r"(dst), "l"(Wc + wsoff[j]));
            }
        }
        asm volatile("cp.async.commit_group;");
    }

    unsigned long long accd[2][XPT];
#pragma unroll
    for (int cp = 0; cp < 2; ++cp)
#pragma unroll
        for (int j = 0; j < XPT; ++j) accd[cp][j] = 0ull;

#pragma unroll 1
    for (int cin = 0; cin < CIN; ++cin) {
        asm volatile("cp.async.wait_group 0;");
        __syncthreads();

        // issue next cin's input + weights into the other buffers
        if (cin + 1 < CIN) {
            const float* Xc = Xb + (size_t)(cin + 1) * (SDIM * SDIM * SDIM);
            float* ibuf = s_in[(cin + 1) & 1];
#pragma unroll
            for (int k = 0; k < IN_SLOTS; ++k) {
                int off = s_soff[k * NTHREADS + tid];
                if (off >= 0) {
                    uint32_t dst = smem_u32(&ibuf[tid + k * NTHREADS]);
                    asm volatile("cp.async.ca.shared.global [%0], [%1], 4;"
                                 :: "r"(dst), "l"(Xc + off));
                }
            }
            const float* Wc = Wg + (cin + 1) * 27;
            float* wbuf = s_wbuf[(cin + 1) & 1];
#pragma unroll
            for (int j = 0; j < W_SLOTS; ++j) {
                if (wsoff[j] >= 0) {
                    uint32_t dst = smem_u32(&wbuf[wdoff[j]]);
                    asm volatile("cp.async.ca.shared.global [%0], [%1], 4;"
                                 :: "r"(dst), "l"(Wc + wsoff[j]));
                }
            }
            asm volatile("cp.async.commit_group;");
        }

        // ---- Compute: conflict-free window loads + FFMA2 over cout pairs ----
        const float* cur = s_in[cin & 1];
        const float* wsl = s_wbuf[cin & 1] + cg * CPT;
#pragma unroll
        for (int kd = 0; kd < 3; ++kd) {
#pragma unroll
            for (int kh = 0; kh < 3; ++kh) {
                const float* rowp = cur + (kd * IN_H + ty + kh) * IN_ROW + tx * WIN_W;
                const float2* r2 = reinterpret_cast<const float2*>(rowp);
                unsigned long long dup[WIN_W];
#pragma unroll
                for (int i = 0; i < 5; ++i) {
                    float2 p = r2[i];
                    PACKF2(dup[2 * i],     p.x, p.x);
                    PACKF2(dup[2 * i + 1], p.y, p.y);
                }

                const float* wp = wsl + (kd * 3 + kh) * 48;
                unsigned long long wA[3], wB[3];
#pragma unroll
                for (int kw = 0; kw < 3; ++kw) {
                    ulonglong2 q = *reinterpret_cast<const ulonglong2*>(wp + kw * 16);
                    wA[kw] = q.x;
                    wB[kw] = q.y;
                }

#pragma unroll
                for (int kw = 0; kw < 3; ++kw)
#pragma unroll
                    for (int j = 0; j < XPT; ++j) {
                        FMAF2(accd[0][j], dup[j + kw], wA[kw], accd[0][j]);
                        FMAF2(accd[1][j], dup[j + kw], wB[kw], accd[1][j]);
                    }
            }
        }
    }

    // ---- Epilogue ----
    const int x0 = tx * XPT;
    const int y  = y0 + ty;
#pragma unroll
    for (int cp = 0; cp < 2; ++cp) {
        float o0[XPT], o1[XPT];
#pragma unroll
        for (int j = 0; j < XPT; ++j) UNPACKF2(o0[j], o1[j], accd[cp][j]);

        const int c0 = cg * CPT + 2 * cp;
        const float b0 = s_bias[c0];
        const float b1 = s_bias[c0 + 1];

        float* op0 = Out + ((((size_t)b * COUTC + c0)     * SDIM + z) * SDIM + y) * SDIM + x0;
        float* op1 = Out + ((((size_t)b * COUTC + c0 + 1) * SDIM + z) * SDIM + y) * SDIM + x0;

        reinterpret_cast<float4*>(op0)[0] = make_float4(o0[0] + b0, o0[1] + b0, o0[2] + b0, o0[3] + b0);
        reinterpret_cast<float4*>(op0)[1] = make_float4(o0[4] + b0, o0[5] + b0, o0[6] + b0, o0[7] + b0);
        reinterpret_cast<float4*>(op1)[0] = make_float4(o1[0] + b1, o1[1] + b1, o1[2] + b1, o1[3] + b1);
        reinterpret_cast<float4*>(op1)[1] = make_float4(o1[4] + b1, o1[5] + b1, o1[6] + b1, o1[7] + b1);
    }
}

extern "C" void kernel_launch(void* const* d_in, const int* in_sizes, int n_in,
                              void* d_out, int out_size)
{
    const float* x    = (const float*)d_in[0];
    const float* w    = (const float*)d_in[1];
    const float* bias = (const float*)d_in[2];
    float* out        = (float*)d_out;

    dim3 grid(SDIM, SDIM / TY, BATCH);
    conv3d_kernel<<<grid, NTHREADS>>>(x, w, bias, out);
}

// round 8
// speedup vs baseline: 1.1977x; 1.0326x over previous
#include <cuda_runtime.h>
#include <cstdint>

// Problem constants
#define SDIM   64
#define CIN    16
#define COUTC  16
#define BATCH  4

// Tiling (16 couts per block, 4 per thread)
#define TY         4
#define TXT        8
#define XPT        8
#define CPT        4
#define NTHREADS 128

// Windowed input tile: 8 windows of 10 floats per row (conflict-free LDS.64)
#define WIN_W      10
#define NWIN       8
#define IN_ROW     (NWIN * WIN_W)     // 80
#define IN_H       (TY + 2)           // 6
#define IN_D       3
#define TILE_ELEMS (IN_D * IN_H * IN_ROW)   // 1440
#define IN_SLOTS   ((TILE_ELEMS + NTHREADS - 1) / NTHREADS)  // 12

// Transposed weights in global scratch: [(cin*3+kd)*3+kh][kw*16 + cout]
#define WT_ELEMS (CIN * 9 * 48)   // 6912

__device__ __align__(16) float g_wt[WT_ELEMS];

#define PACKF2(d, lo, hi) \
    asm("mov.b64 %0, {%1, %2};" : "=l"(d) : "f"(lo), "f"(hi))
#define FMAF2(d, a, b, c) \
    asm("fma.rn.f32x2 %0, %1, %2, %3;" : "=l"(d) : "l"(a), "l"(b), "l"(c))
#define UNPACKF2(lo, hi, s) \
    asm("mov.b64 {%0, %1}, %2;" : "=f"(lo), "=f"(hi) : "l"(s))

__device__ __forceinline__ uint32_t smem_u32(const void* p) {
    return (uint32_t)__cvta_generic_to_shared(p);
}

// ---- Pre-kernel: transpose weights into broadcast-friendly layout ----
__global__ void transpose_w_kernel(const float* __restrict__ Wg)
{
    int g = blockIdx.x * blockDim.x + threadIdx.x;
    if (g < COUTC * CIN * 27) {
        int cout = g / (CIN * 27);
        int rem  = g % (CIN * 27);
        int cin  = rem / 27;
        int k    = rem % 27;
        g_wt[(cin * 9 + k / 3) * 48 + (k % 3) * 16 + cout] = Wg[g];
    }
}

__global__ void __launch_bounds__(NTHREADS, 6)
conv3d_kernel(const float* __restrict__ X,
              const float* __restrict__ Bias,
              float* __restrict__ Out)
{
    __shared__ __align__(16) float s_in[2][TILE_ELEMS];      // 11.5 KB
    __shared__ int   s_soff[IN_SLOTS * NTHREADS];            // 6 KB
    __shared__ float s_bias[COUTC];

    const int tid = threadIdx.x;
    const int tx  = tid & (TXT - 1);
    const int ty  = (tid >> 3) & (TY - 1);
    const int cg  = tid >> 5;

    const int z  = blockIdx.x;
    const int y0 = blockIdx.y * TY;
    const int b  = blockIdx.z;

    // ---- Precompute input tile-slot source offsets -> shared (cin-invariant) ----
    for (int k = 0; k < IN_SLOTS; ++k) {
        int s = tid + k * NTHREADS;
        int off = -1;
        if (s < TILE_ELEMS) {
            int r  = s / IN_ROW;
            int p  = s % IN_ROW;
            int w  = p / WIN_W;
            int o  = p % WIN_W;
            int gx = 8 * w + o - 1;
            int gz = z  + r / IN_H - 1;
            int gy = y0 + r % IN_H - 1;
            if ((unsigned)gz < SDIM && (unsigned)gy < SDIM && (unsigned)gx < SDIM)
                off = (gz * SDIM + gy) * SDIM + gx;
            else {
                s_in[0][s] = 0.0f;    // zero halo once in both buffers
                s_in[1][s] = 0.0f;
            }
        }
        s_soff[k * NTHREADS + tid] = off;
    }
    if (tid < COUTC) s_bias[tid] = Bias[tid];
    __syncthreads();   // halo zeros + s_soff visible

    const float* Xb = X + (size_t)b * CIN * (SDIM * SDIM * SDIM);

    // ---- Prologue: async-load input tile for cin=0 ----
    {
#pragma unroll
        for (int k = 0; k < IN_SLOTS; ++k) {
            int off = s_soff[k * NTHREADS + tid];
            if (off >= 0) {
                uint32_t dst = smem_u32(&s_in[0][tid + k * NTHREADS]);
                asm volatile("cp.async.ca.shared.global [%0], [%1], 4;"
                             :: "r"(dst), "l"(Xb + off));
            }
        }
        asm volatile("cp.async.commit_group;");
    }

    unsigned long long accd[2][XPT];
#pragma unroll
    for (int cp = 0; cp < 2; ++cp)
#pragma unroll
        for (int j = 0; j < XPT; ++j) accd[cp][j] = 0ull;

#pragma unroll 1
    for (int cin = 0; cin < CIN; ++cin) {
        asm volatile("cp.async.wait_group 0;");
        __syncthreads();

        // issue next cin's input into the other buffer
        if (cin + 1 < CIN) {
            const float* Xc = Xb + (size_t)(cin + 1) * (SDIM * SDIM * SDIM);
            float* ibuf = s_in[(cin + 1) & 1];
#pragma unroll
            for (int k = 0; k < IN_SLOTS; ++k) {
                int off = s_soff[k * NTHREADS + tid];
                if (off >= 0) {
                    uint32_t dst = smem_u32(&ibuf[tid + k * NTHREADS]);
                    asm volatile("cp.async.ca.shared.global [%0], [%1], 4;"
                                 :: "r"(dst), "l"(Xc + off));
                }
            }
            asm volatile("cp.async.commit_group;");
        }

        // ---- Compute: conflict-free window LDS + L1-broadcast weight LDG ----
        const float* cur = s_in[cin & 1];
        const float* wci = g_wt + cin * (9 * 48) + cg * CPT;
#pragma unroll
        for (int kd = 0; kd < 3; ++kd) {
#pragma unroll
            for (int kh = 0; kh < 3; ++kh) {
                // weights: one LDG.128 broadcast per kw (16B-aligned), zero repack
                const float* wp = wci + (kd * 3 + kh) * 48;
                unsigned long long wA[3], wB[3];
#pragma unroll
                for (int kw = 0; kw < 3; ++kw) {
                    ulonglong2 q = __ldg(reinterpret_cast<const ulonglong2*>(wp + kw * 16));
                    wA[kw] = q.x;
                    wB[kw] = q.y;
                }

                const float* rowp = cur + (kd * IN_H + ty + kh) * IN_ROW + tx * WIN_W;
                const float2* r2 = reinterpret_cast<const float2*>(rowp);
                unsigned long long dup[WIN_W];
#pragma unroll
                for (int i = 0; i < 5; ++i) {
                    float2 p = r2[i];
                    PACKF2(dup[2 * i],     p.x, p.x);
                    PACKF2(dup[2 * i + 1], p.y, p.y);
                }

#pragma unroll
                for (int kw = 0; kw < 3; ++kw)
#pragma unroll
                    for (int j = 0; j < XPT; ++j) {
                        FMAF2(accd[0][j], dup[j + kw], wA[kw], accd[0][j]);
                        FMAF2(accd[1][j], dup[j + kw], wB[kw], accd[1][j]);
                    }
            }
        }
    }

    // ---- Epilogue ----
    const int x0 = tx * XPT;
    const int y  = y0 + ty;
#pragma unroll
    for (int cp = 0; cp < 2; ++cp) {
        float o0[XPT], o1[XPT];
#pragma unroll
        for (int j = 0; j < XPT; ++j) UNPACKF2(o0[j], o1[j], accd[cp][j]);

        const int c0 = cg * CPT + 2 * cp;
        const float b0 = s_bias[c0];
        const float b1 = s_bias[c0 + 1];

        float* op0 = Out + ((((size_t)b * COUTC + c0)     * SDIM + z) * SDIM + y) * SDIM + x0;
        float* op1 = Out + ((((size_t)b * COUTC + c0 + 1) * SDIM + z) * SDIM + y) * SDIM + x0;

        reinterpret_cast<float4*>(op0)[0] = make_float4(o0[0] + b0, o0[1] + b0, o0[2] + b0, o0[3] + b0);
        reinterpret_cast<float4*>(op0)[1] = make_float4(o0[4] + b0, o0[5] + b0, o0[6] + b0, o0[7] + b0);
        reinterpret_cast<float4*>(op1)[0] = make_float4(o1[0] + b1, o1[1] + b1, o1[2] + b1, o1[3] + b1);
        reinterpret_cast<float4*>(op1)[1] = make_float4(o1[4] + b1, o1[5] + b1, o1[6] + b1, o1[7] + b1);
    }
}

extern "C" void kernel_launch(void* const* d_in, const int* in_sizes, int n_in,
                              void* d_out, int out_size)
{
    const float* x    = (const float*)d_in[0];
    const float* w    = (const float*)d_in[1];
    const float* bias = (const float*)d_in[2];
    float* out        = (float*)d_out;

    // 1) transpose weights into g_wt (tiny)
    transpose_w_kernel<<<(COUTC * CIN * 27 + NTHREADS - 1) / NTHREADS, NTHREADS>>>(w);

    // 2) main conv
    dim3 grid(SDIM, SDIM / TY, BATCH);
    conv3d_kernel<<<grid, NTHREADS>>>(x, bias, out);
}